// round 11
// baseline (speedup 1.0000x reference)
#include <cuda_runtime.h>
#include <cuda_fp16.h>
#include <math.h>
#include <stdint.h>

// Problem constants
#define BATCH 2
#define SEQ   2048
#define DMODEL 1024
#define NHEADS 16
#define HDIM  64
#define MTOT  (BATCH * SEQ)            // 4096
#define QKV_LD (3 * DMODEL)            // 3072
#define FL_SCALE 0.1803368801111244f   // 0.125 * log2(e)
#define NSM    148
#define GEMM_GRID (2 * NSM)            // persistent CTAs (2/SM)

// -------- scratch (no allocations allowed -> __device__ globals) --------
__device__ __half g_QKV [(size_t)MTOT * QKV_LD];          // fused QKV output
__device__ __half g_Ctxh[(size_t)MTOT * DMODEL];
__device__ __half g_Xh  [(size_t)MTOT * DMODEL];
__device__ __half g_Wcat[(size_t)QKV_LD * DMODEL];        // [Wq;Wk;Wv]
__device__ __half g_Woh [(size_t)DMODEL * DMODEL];

// ================= helpers =================
__device__ __forceinline__ uint32_t smem_u32(const void* p) {
    uint32_t a;
    asm("{ .reg .u64 t; cvta.to.shared.u64 t, %1; cvt.u32.u64 %0, t; }"
        : "=r"(a) : "l"(p));
    return a;
}

#define SWZ128(x) ((x) ^ (((x) >> 3) & 0x70))

#define CP_ASYNC16(dst, src) \
    asm volatile("cp.async.cg.shared.global [%0], [%1], 16;" \
                 :: "r"(dst), "l"(src) : "memory")
#define CP_ASYNC_COMMIT() asm volatile("cp.async.commit_group;" ::: "memory")

#define LDSM_X4(r, addr) \
    asm volatile("ldmatrix.sync.aligned.m8n8.x4.shared.b16 {%0,%1,%2,%3}, [%4];" \
        : "=r"((r)[0]), "=r"((r)[1]), "=r"((r)[2]), "=r"((r)[3]) : "r"(addr))

#define LDSM_X4_T(r, addr) \
    asm volatile("ldmatrix.sync.aligned.m8n8.x4.trans.shared.b16 {%0,%1,%2,%3}, [%4];" \
        : "=r"((r)[0]), "=r"((r)[1]), "=r"((r)[2]), "=r"((r)[3]) : "r"(addr))

#define MMA16816(d, a, b0, b1) \
    asm volatile("mma.sync.aligned.m16n8k16.row.col.f32.f16.f16.f32 " \
        "{%0,%1,%2,%3}, {%4,%5,%6,%7}, {%8,%9}, {%0,%1,%2,%3};" \
        : "+f"((d)[0]), "+f"((d)[1]), "+f"((d)[2]), "+f"((d)[3]) \
        : "r"((a)[0]), "r"((a)[1]), "r"((a)[2]), "r"((a)[3]), "r"(b0), "r"(b1))

__device__ __forceinline__ uint32_t packh2(float a, float b) {
    __half2 h = __floats2half2_rn(a, b);
    return *reinterpret_cast<uint32_t*>(&h);
}

__device__ __forceinline__ uint32_t hmul2u(uint32_t a, uint32_t b) {
    __half2 r = __hmul2(*reinterpret_cast<__half2*>(&a),
                        *reinterpret_cast<__half2*>(&b));
    return *reinterpret_cast<uint32_t*>(&r);
}

// single-instruction exponential (base 2); flushes large-negative to +0
__device__ __forceinline__ float ex2(float x) {
    float y;
    asm("ex2.approx.f32 %0, %1;" : "=f"(y) : "f"(x));
    return y;
}

// ============================================================
// conversions
// ============================================================
__global__ void f2h_kernel(const float* __restrict__ src,
                           __half* __restrict__ dst, int n)
{
    int i = (blockIdx.x * blockDim.x + threadIdx.x) * 4;
    if (i >= n) return;
    float4 v = *(const float4*)(src + i);
    *(__half2*)(dst + i)     = __floats2half2_rn(v.x, v.y);
    *(__half2*)(dst + i + 2) = __floats2half2_rn(v.z, v.w);
}

__global__ void f2h3_kernel(const float* __restrict__ s0,
                            const float* __restrict__ s1,
                            const float* __restrict__ s2,
                            __half* __restrict__ dst, int nPer)
{
    int i = (blockIdx.x * blockDim.x + threadIdx.x) * 4;
    if (i >= 3 * nPer) return;
    const float* src = (i < nPer) ? s0 : (i < 2 * nPer) ? s1 : s2;
    int j = i - ((i < nPer) ? 0 : (i < 2 * nPer) ? nPer : 2 * nPer);
    float4 v = *(const float4*)(src + j);
    *(__half2*)(dst + i)     = __floats2half2_rn(v.x, v.y);
    *(__half2*)(dst + i + 2) = __floats2half2_rn(v.z, v.w);
}

// ============================================================
// fp16 HMMA GEMM (NT), PERSISTENT: C[M,N] = A[M,K]*B[N,K]^T (+bias)
// grid = GEMM_GRID CTAs; each loops tiles with stride gridDim.x.
// 128x128 tile, BK=64, 8 warps, 3-stage cp.async, 2 CTAs/SM.
// ============================================================
#define HG_STAGE 32768                 // A 16K + B 16K per stage
#define HG_SMEM  (3 * HG_STAGE)        // 96 KB

template <typename OT>
__global__ __launch_bounds__(256, 2)
void hgemm_nt(const __half* __restrict__ A,
              const __half* __restrict__ B,
              const float* __restrict__ bias,
              OT* __restrict__ C,
              int M, int N, int K)
{
    extern __shared__ char sm[];
    const uint32_t smem_base = smem_u32(sm);
    const int tid  = threadIdx.x;
    const int lane = tid & 31;
    const int wid  = tid >> 5;
    const int warp_m = (wid >> 2) * 64;
    const int warp_n = (wid & 3) * 32;

    const int tilesN = N / 128;
    const int nTiles = (M / 128) * tilesN;
    const int nchunks = K / 64;

    for (int tile = blockIdx.x; tile < nTiles; tile += gridDim.x) {
        const int m0 = (tile / tilesN) * 128;
        const int n0 = (tile % tilesN) * 128;

        float d[4][4][4];
        #pragma unroll
        for (int mt = 0; mt < 4; mt++)
            #pragma unroll
            for (int nt = 0; nt < 4; nt++)
                #pragma unroll
                for (int r = 0; r < 4; r++) d[mt][nt][r] = 0.0f;

        auto load_chunk = [&](int c, int stage) {
            const uint32_t aBase = smem_base + stage * HG_STAGE;
            const uint32_t bBase = aBase + 16384;
            const char* Ag = (const char*)(A + (size_t)m0 * K + c * 64);
            const char* Bg = (const char*)(B + (size_t)n0 * K + c * 64);
            #pragma unroll
            for (int t = 0; t < 4; t++) {
                int g   = tid + t * 256;
                int row = g >> 3;
                int seg = g & 7;
                uint32_t sw = SWZ128((uint32_t)(row * 128 + seg * 16));
                CP_ASYNC16(aBase + sw, Ag + (size_t)row * K * 2 + seg * 16);
                CP_ASYNC16(bBase + sw, Bg + (size_t)row * K * 2 + seg * 16);
            }
            CP_ASYNC_COMMIT();
        };

        load_chunk(0, 0);
        load_chunk(1, 1);

        for (int c = 0; c < nchunks; c++) {
            if (c + 1 < nchunks) {
                asm volatile("cp.async.wait_group 1;" ::: "memory");
            } else {
                asm volatile("cp.async.wait_group 0;" ::: "memory");
            }
            __syncthreads();
            if (c + 2 < nchunks) load_chunk(c + 2, (c + 2) % 3);

            const uint32_t aBase = smem_base + (c % 3) * HG_STAGE;
            const uint32_t bBase = aBase + 16384;

            #pragma unroll
            for (int ks = 0; ks < 4; ks++) {
                uint32_t a[4][4], b[2][4];
                const int kbyte = ks * 32 + ((lane >> 4) << 4);
                #pragma unroll
                for (int mt = 0; mt < 4; mt++) {
                    const int row = warp_m + mt * 16 + (lane & 15);
                    LDSM_X4(a[mt], aBase + SWZ128((uint32_t)(row * 128 + kbyte)));
                }
                #pragma unroll
                for (int nt2 = 0; nt2 < 2; nt2++) {
                    const int row = warp_n + nt2 * 16 + (lane & 15);
                    LDSM_X4(b[nt2], bBase + SWZ128((uint32_t)(row * 128 + kbyte)));
                }
                #pragma unroll
                for (int mt = 0; mt < 4; mt++)
                    #pragma unroll
                    for (int nt = 0; nt < 4; nt++) {
                        const uint32_t b0 = b[nt >> 1][(nt & 1) ? 1 : 0];
                        const uint32_t b1 = b[nt >> 1][(nt & 1) ? 3 : 2];
                        MMA16816(d[mt][nt], a[mt], b0, b1);
                    }
            }
        }

        #pragma unroll
        for (int mt = 0; mt < 4; mt++) {
            const int row = m0 + warp_m + mt * 16 + (lane >> 2);
            #pragma unroll
            for (int nt = 0; nt < 4; nt++) {
                const int col = n0 + warp_n + nt * 8 + (lane & 3) * 2;
                float bx = 0.0f, by = 0.0f;
                if (bias) { bx = bias[col]; by = bias[col + 1]; }
                float v00 = d[mt][nt][0] + bx, v01 = d[mt][nt][1] + by;
                float v10 = d[mt][nt][2] + bx, v11 = d[mt][nt][3] + by;
                if constexpr (sizeof(OT) == 2) {
                    *(__half2*)((__half*)C + (size_t)row * N + col) =
                        __floats2half2_rn(v00, v01);
                    *(__half2*)((__half*)C + (size_t)(row + 8) * N + col) =
                        __floats2half2_rn(v10, v11);
                } else {
                    float2 a0 = { v00, v01 }, a1 = { v10, v11 };
                    *(float2*)((float*)C + (size_t)row * N + col)       = a0;
                    *(float2*)((float*)C + (size_t)(row + 8) * N + col) = a1;
                }
            }
        }
        // make sure all warps finished reading this tile's smem before
        // the next tile's prologue overwrites it
        __syncthreads();
    }
}

// ============================================================
// fp16 HMMA flash attention (causal), 3-stage KV pipeline,
// 2 CTAs/SM, pre-scaled Q fragments, ex2.approx softmax.
// HEAVY-FIRST: qt = gridDim.x-1-blockIdx.x so the largest
// causal workloads start in the first wave.
// ============================================================
#define FL_Q_OFF  0                    // 16 KB
#define FL_KV_OFF 16384                // 3 stages x (K 8K + V 8K)
#define FL_STAGE  16384
#define FL_SMEM   (16384 + 3 * FL_STAGE)   // 64 KB

__global__ __launch_bounds__(256, 2)
void flash_hmma(const __half* __restrict__ QKV,
                __half* __restrict__ Ctx)
{
    extern __shared__ char sm[];
    const uint32_t smem_base = smem_u32(sm);
    const int tid  = threadIdx.x;
    const int lane = tid & 31;
    const int wid  = tid >> 5;
    const int warp_m = wid * 16;
    const int q0 = (gridDim.x - 1 - blockIdx.x) * 128;   // heavy-first
    const int h  = blockIdx.y;
    const int b  = blockIdx.z;

    const size_t rowBase = (size_t)b * SEQ * QKV_LD + (size_t)h * HDIM;
    const __half* Q = QKV + rowBase;
    const __half* K = QKV + rowBase + DMODEL;
    const __half* V = QKV + rowBase + 2 * DMODEL;

    const int ntiles = (q0 + 128) / 64;

    auto load_kv = [&](int jt, int stage) {
        const uint32_t kBase = smem_base + FL_KV_OFF + stage * FL_STAGE;
        const uint32_t vBase = kBase + 8192;
        const int k0 = jt * 64;
        #pragma unroll
        for (int t = 0; t < 2; t++) {
            int g   = tid + t * 256;
            int row = g >> 3;
            int seg = g & 7;
            uint32_t sw = SWZ128((uint32_t)(row * 128 + seg * 16));
            CP_ASYNC16(kBase + sw, (const char*)(K + (size_t)(k0 + row) * QKV_LD + seg * 8));
            CP_ASYNC16(vBase + sw, (const char*)(V + (size_t)(k0 + row) * QKV_LD + seg * 8));
        }
        CP_ASYNC_COMMIT();
    };

    {
        #pragma unroll
        for (int t = 0; t < 4; t++) {
            int g   = tid + t * 256;
            int row = g >> 3;
            int seg = g & 7;
            uint32_t sw = SWZ128((uint32_t)(row * 128 + seg * 16));
            CP_ASYNC16(smem_base + FL_Q_OFF + sw,
                       (const char*)(Q + (size_t)(q0 + row) * QKV_LD + seg * 8));
        }
        CP_ASYNC_COMMIT();
    }
    load_kv(0, 0);
    if (ntiles > 1) load_kv(1, 1);

    if (ntiles > 1) {
        asm volatile("cp.async.wait_group 1;" ::: "memory");
    } else {
        asm volatile("cp.async.wait_group 0;" ::: "memory");
    }
    __syncthreads();

    // Q fragments, pre-scaled by FL_SCALE in fp16 (16 HMUL2, once)
    uint32_t qa[4][4];
    {
        __half2 a2 = __float2half2_rn(FL_SCALE);
        const uint32_t au = *reinterpret_cast<uint32_t*>(&a2);
        #pragma unroll
        for (int ks = 0; ks < 4; ks++) {
            const int row   = warp_m + (lane & 15);
            const int kbyte = ks * 32 + ((lane >> 4) << 4);
            LDSM_X4(qa[ks], smem_base + FL_Q_OFF + SWZ128((uint32_t)(row * 128 + kbyte)));
            #pragma unroll
            for (int i = 0; i < 4; i++) qa[ks][i] = hmul2u(qa[ks][i], au);
        }
    }

    float m1 = -1e30f, m2 = -1e30f, l1 = 0.0f, l2 = 0.0f;
    float o[8][4];
    #pragma unroll
    for (int t = 0; t < 8; t++)
        #pragma unroll
        for (int r = 0; r < 4; r++) o[t][r] = 0.0f;

    const int g = lane >> 2;
    const int r1 = q0 + warp_m + g;
    const int r2 = r1 + 8;
    const int cbase = (lane & 3) * 2;

    for (int jt = 0; jt < ntiles; jt++) {
        if (jt > 0) {
            if (jt + 1 < ntiles) {
                asm volatile("cp.async.wait_group 1;" ::: "memory");
            } else {
                asm volatile("cp.async.wait_group 0;" ::: "memory");
            }
            __syncthreads();
        }
        if (jt + 2 < ntiles) load_kv(jt + 2, (jt + 2) % 3);

        const int k0 = jt * 64;
        const uint32_t kBase = smem_base + FL_KV_OFF + (jt % 3) * FL_STAGE;
        const uint32_t vBase = kBase + 8192;

        // ---- S = (alpha*Q) K^T  (log2 domain) ----
        float s[8][4];
        #pragma unroll
        for (int t = 0; t < 8; t++)
            #pragma unroll
            for (int r = 0; r < 4; r++) s[t][r] = 0.0f;

        #pragma unroll
        for (int ks = 0; ks < 4; ks++) {
            const int kbyte = ks * 32 + ((lane >> 4) << 4);
            #pragma unroll
            for (int nb = 0; nb < 4; nb++) {
                uint32_t kb[4];
                const int row = nb * 16 + (lane & 15);
                LDSM_X4(kb, kBase + SWZ128((uint32_t)(row * 128 + kbyte)));
                MMA16816(s[nb * 2],     qa[ks], kb[0], kb[2]);
                MMA16816(s[nb * 2 + 1], qa[ks], kb[1], kb[3]);
            }
        }

        // ---- causal mask ----
        if (k0 + 63 > q0 + warp_m) {
            #pragma unroll
            for (int t = 0; t < 8; t++) {
                const int c0 = k0 + t * 8 + cbase;
                if (c0 > r1)     s[t][0] = -1e30f;
                if (c0 + 1 > r1) s[t][1] = -1e30f;
                if (c0 > r2)     s[t][2] = -1e30f;
                if (c0 + 1 > r2) s[t][3] = -1e30f;
            }
        }

        // ---- online softmax (base-2, pre-scaled) ----
        float mx1 = -1e30f, mx2 = -1e30f;
        #pragma unroll
        for (int t = 0; t < 8; t++) {
            mx1 = fmaxf(mx1, fmaxf(s[t][0], s[t][1]));
            mx2 = fmaxf(mx2, fmaxf(s[t][2], s[t][3]));
        }
        mx1 = fmaxf(mx1, __shfl_xor_sync(0xffffffffu, mx1, 1));
        mx1 = fmaxf(mx1, __shfl_xor_sync(0xffffffffu, mx1, 2));
        mx2 = fmaxf(mx2, __shfl_xor_sync(0xffffffffu, mx2, 1));
        mx2 = fmaxf(mx2, __shfl_xor_sync(0xffffffffu, mx2, 2));

        const float mn1 = fmaxf(m1, mx1), mn2 = fmaxf(m2, mx2);
        const float sc1 = ex2(m1 - mn1);
        const float sc2 = ex2(m2 - mn2);
        float sum1 = 0.0f, sum2 = 0.0f;
        #pragma unroll
        for (int t = 0; t < 8; t++) {
            s[t][0] = ex2(s[t][0] - mn1); sum1 += s[t][0];
            s[t][1] = ex2(s[t][1] - mn1); sum1 += s[t][1];
            s[t][2] = ex2(s[t][2] - mn2); sum2 += s[t][2];
            s[t][3] = ex2(s[t][3] - mn2); sum2 += s[t][3];
        }
        sum1 += __shfl_xor_sync(0xffffffffu, sum1, 1);
        sum1 += __shfl_xor_sync(0xffffffffu, sum1, 2);
        sum2 += __shfl_xor_sync(0xffffffffu, sum2, 1);
        sum2 += __shfl_xor_sync(0xffffffffu, sum2, 2);

        l1 = l1 * sc1 + sum1;
        l2 = l2 * sc2 + sum2;
        m1 = mn1; m2 = mn2;

        #pragma unroll
        for (int t = 0; t < 8; t++) {
            o[t][0] *= sc1; o[t][1] *= sc1;
            o[t][2] *= sc2; o[t][3] *= sc2;
        }

        // ---- P fragments ----
        uint32_t pa[4][4];
        #pragma unroll
        for (int ks = 0; ks < 4; ks++) {
            pa[ks][0] = packh2(s[2 * ks][0],     s[2 * ks][1]);
            pa[ks][1] = packh2(s[2 * ks][2],     s[2 * ks][3]);
            pa[ks][2] = packh2(s[2 * ks + 1][0], s[2 * ks + 1][1]);
            pa[ks][3] = packh2(s[2 * ks + 1][2], s[2 * ks + 1][3]);
        }

        // ---- O += P V ----
        #pragma unroll
        for (int ks = 0; ks < 4; ks++) {
            const int crow = ks * 16 + (lane & 15);
            #pragma unroll
            for (int db = 0; db < 4; db++) {
                uint32_t vb[4];
                const int dbyte = db * 32 + ((lane >> 4) << 4);
                LDSM_X4_T(vb, vBase + SWZ128((uint32_t)(crow * 128 + dbyte)));
                MMA16816(o[db * 2],     pa[ks], vb[0], vb[1]);
                MMA16816(o[db * 2 + 1], pa[ks], vb[2], vb[3]);
            }
        }
    }

    // ---- normalize + write ctx ----
    const size_t ctxBase = (size_t)b * SEQ * DMODEL + (size_t)h * HDIM;
    const float inv1 = 1.0f / l1, inv2 = 1.0f / l2;
    #pragma unroll
    for (int t = 0; t < 8; t++) {
        const int col = t * 8 + cbase;
        *(__half2*)(Ctx + ctxBase + (size_t)r1 * DMODEL + col) =
            __floats2half2_rn(o[t][0] * inv1, o[t][1] * inv1);
        *(__half2*)(Ctx + ctxBase + (size_t)r2 * DMODEL + col) =
            __floats2half2_rn(o[t][2] * inv2, o[t][3] * inv2);
    }
}

// ============================================================
extern "C" void kernel_launch(void* const* d_in, const int* in_sizes, int n_in,
                              void* d_out, int out_size)
{
    const float* x  = (const float*)d_in[0];
    const float* Wq = (const float*)d_in[1];
    const float* Wk = (const float*)d_in[2];
    const float* Wv = (const float*)d_in[3];
    const float* Wo = (const float*)d_in[4];
    const float* bo = (const float*)d_in[5];
    float* out = (float*)d_out;

    __half *QKVh, *Ch, *Xh, *Wcat, *Woh;
    cudaGetSymbolAddress((void**)&QKVh, g_QKV);
    cudaGetSymbolAddress((void**)&Ch,   g_Ctxh);
    cudaGetSymbolAddress((void**)&Xh,   g_Xh);
    cudaGetSymbolAddress((void**)&Wcat, g_Wcat);
    cudaGetSymbolAddress((void**)&Woh,  g_Woh);

    cudaFuncSetAttribute(hgemm_nt<__half>,
                         cudaFuncAttributeMaxDynamicSharedMemorySize, HG_SMEM);
    cudaFuncSetAttribute(hgemm_nt<float>,
                         cudaFuncAttributeMaxDynamicSharedMemorySize, HG_SMEM);
    cudaFuncSetAttribute(flash_hmma,
                         cudaFuncAttributeMaxDynamicSharedMemorySize, FL_SMEM);

    const int nX = MTOT * DMODEL, nW = DMODEL * DMODEL;
    f2h_kernel <<<nX / 4 / 256, 256>>>(x, Xh, nX);
    f2h3_kernel<<<3 * nW / 4 / 256, 256>>>(Wq, Wk, Wv, Wcat, nW);
    f2h_kernel <<<nW / 4 / 256, 256>>>(Wo, Woh, nW);

    // fused QKV projection: [4096 x 3072], persistent grid
    hgemm_nt<__half><<<GEMM_GRID, 256, HG_SMEM>>>(Xh, Wcat, nullptr, QKVh,
                                                  MTOT, QKV_LD, DMODEL);

    dim3 gFa(SEQ / 128, NHEADS, BATCH);     // (16, 16, 2)
    flash_hmma<<<gFa, 256, FL_SMEM>>>(QKVh, Ch);

    // output projection: 256 tiles < 296 CTAs -> single pass
    hgemm_nt<float><<<GEMM_GRID, 256, HG_SMEM>>>(Ch, Woh, bo, out,
                                                 MTOT, DMODEL, DMODEL);
}

// round 16
// speedup vs baseline: 1.0361x; 1.0361x over previous
#include <cuda_runtime.h>
#include <cuda_fp16.h>
#include <math.h>
#include <stdint.h>

// Problem constants
#define BATCH 2
#define SEQ   2048
#define DMODEL 1024
#define NHEADS 16
#define HDIM  64
#define MTOT  (BATCH * SEQ)            // 4096
#define QKV_LD (3 * DMODEL)            // 3072
#define FL_SCALE 0.1803368801111244f   // 0.125 * log2(e)

// -------- scratch (no allocations allowed -> __device__ globals) --------
__device__ __half g_QKV [(size_t)MTOT * QKV_LD];          // fused QKV output
__device__ __half g_Ctxh[(size_t)MTOT * DMODEL];
__device__ __half g_Xh  [(size_t)MTOT * DMODEL];
__device__ __half g_Wcat[(size_t)QKV_LD * DMODEL];        // [Wq;Wk;Wv]
__device__ __half g_Woh [(size_t)DMODEL * DMODEL];

// ================= helpers =================
__device__ __forceinline__ uint32_t smem_u32(const void* p) {
    uint32_t a;
    asm("{ .reg .u64 t; cvta.to.shared.u64 t, %1; cvt.u32.u64 %0, t; }"
        : "=r"(a) : "l"(p));
    return a;
}

#define SWZ128(x) ((x) ^ (((x) >> 3) & 0x70))

#define CP_ASYNC16(dst, src) \
    asm volatile("cp.async.cg.shared.global [%0], [%1], 16;" \
                 :: "r"(dst), "l"(src) : "memory")
#define CP_ASYNC_COMMIT() asm volatile("cp.async.commit_group;" ::: "memory")

#define LDSM_X4(r, addr) \
    asm volatile("ldmatrix.sync.aligned.m8n8.x4.shared.b16 {%0,%1,%2,%3}, [%4];" \
        : "=r"((r)[0]), "=r"((r)[1]), "=r"((r)[2]), "=r"((r)[3]) : "r"(addr))

#define LDSM_X4_T(r, addr) \
    asm volatile("ldmatrix.sync.aligned.m8n8.x4.trans.shared.b16 {%0,%1,%2,%3}, [%4];" \
        : "=r"((r)[0]), "=r"((r)[1]), "=r"((r)[2]), "=r"((r)[3]) : "r"(addr))

#define MMA16816(d, a, b0, b1) \
    asm volatile("mma.sync.aligned.m16n8k16.row.col.f32.f16.f16.f32 " \
        "{%0,%1,%2,%3}, {%4,%5,%6,%7}, {%8,%9}, {%0,%1,%2,%3};" \
        : "+f"((d)[0]), "+f"((d)[1]), "+f"((d)[2]), "+f"((d)[3]) \
        : "r"((a)[0]), "r"((a)[1]), "r"((a)[2]), "r"((a)[3]), "r"(b0), "r"(b1))

__device__ __forceinline__ uint32_t packh2(float a, float b) {
    __half2 h = __floats2half2_rn(a, b);
    return *reinterpret_cast<uint32_t*>(&h);
}

__device__ __forceinline__ uint32_t hmul2u(uint32_t a, uint32_t b) {
    __half2 r = __hmul2(*reinterpret_cast<__half2*>(&a),
                        *reinterpret_cast<__half2*>(&b));
    return *reinterpret_cast<uint32_t*>(&r);
}

// single-instruction exponential (base 2); flushes large-negative to +0
__device__ __forceinline__ float ex2(float x) {
    float y;
    asm("ex2.approx.f32 %0, %1;" : "=f"(y) : "f"(x));
    return y;
}

// ============================================================
// conversions
// ============================================================
__global__ void f2h_kernel(const float* __restrict__ src,
                           __half* __restrict__ dst, int n)
{
    int i = (blockIdx.x * blockDim.x + threadIdx.x) * 4;
    if (i >= n) return;
    float4 v = *(const float4*)(src + i);
    *(__half2*)(dst + i)     = __floats2half2_rn(v.x, v.y);
    *(__half2*)(dst + i + 2) = __floats2half2_rn(v.z, v.w);
}

__global__ void f2h3_kernel(const float* __restrict__ s0,
                            const float* __restrict__ s1,
                            const float* __restrict__ s2,
                            __half* __restrict__ dst, int nPer)
{
    int i = (blockIdx.x * blockDim.x + threadIdx.x) * 4;
    if (i >= 3 * nPer) return;
    const float* src = (i < nPer) ? s0 : (i < 2 * nPer) ? s1 : s2;
    int j = i - ((i < nPer) ? 0 : (i < 2 * nPer) ? nPer : 2 * nPer);
    float4 v = *(const float4*)(src + j);
    *(__half2*)(dst + i)     = __floats2half2_rn(v.x, v.y);
    *(__half2*)(dst + i + 2) = __floats2half2_rn(v.z, v.w);
}

// ============================================================
// fp16 HMMA GEMM (NT): C[M,N] = A[M,K] * B[N,K]^T (+bias)
// 128x128 CTA tile, BK=64, 8 warps, 3-stage cp.async pipeline
// with ONE __syncthreads per chunk, 2 CTAs/SM.  (round-10 version)
// ============================================================
#define HG_STAGE 32768                 // A 16K + B 16K per stage
#define HG_SMEM  (3 * HG_STAGE)        // 96 KB

template <typename OT>
__global__ __launch_bounds__(256, 2)
void hgemm_nt(const __half* __restrict__ A,
              const __half* __restrict__ B,
              const float* __restrict__ bias,
              OT* __restrict__ C,
              int M, int N, int K)
{
    extern __shared__ char sm[];
    const uint32_t smem_base = smem_u32(sm);
    const int tid  = threadIdx.x;
    const int lane = tid & 31;
    const int wid  = tid >> 5;
    const int m0 = blockIdx.y * 128;
    const int n0 = blockIdx.x * 128;
    const int warp_m = (wid >> 2) * 64;
    const int warp_n = (wid & 3) * 32;

    float d[4][4][4];
    #pragma unroll
    for (int mt = 0; mt < 4; mt++)
        #pragma unroll
        for (int nt = 0; nt < 4; nt++)
            #pragma unroll
            for (int r = 0; r < 4; r++) d[mt][nt][r] = 0.0f;

    const int nchunks = K / 64;

    auto load_chunk = [&](int c, int stage) {
        const uint32_t aBase = smem_base + stage * HG_STAGE;
        const uint32_t bBase = aBase + 16384;
        const char* Ag = (const char*)(A + (size_t)m0 * K + c * 64);
        const char* Bg = (const char*)(B + (size_t)n0 * K + c * 64);
        #pragma unroll
        for (int t = 0; t < 4; t++) {
            int g   = tid + t * 256;
            int row = g >> 3;
            int seg = g & 7;
            uint32_t sw = SWZ128((uint32_t)(row * 128 + seg * 16));
            CP_ASYNC16(aBase + sw, Ag + (size_t)row * K * 2 + seg * 16);
            CP_ASYNC16(bBase + sw, Bg + (size_t)row * K * 2 + seg * 16);
        }
        CP_ASYNC_COMMIT();
    };

    load_chunk(0, 0);
    if (nchunks > 1) load_chunk(1, 1);

    for (int c = 0; c < nchunks; c++) {
        if (c + 1 < nchunks) {
            asm volatile("cp.async.wait_group 1;" ::: "memory");
        } else {
            asm volatile("cp.async.wait_group 0;" ::: "memory");
        }
        __syncthreads();
        if (c + 2 < nchunks) load_chunk(c + 2, (c + 2) % 3);

        const uint32_t aBase = smem_base + (c % 3) * HG_STAGE;
        const uint32_t bBase = aBase + 16384;

        #pragma unroll
        for (int ks = 0; ks < 4; ks++) {
            uint32_t a[4][4], b[2][4];
            const int kbyte = ks * 32 + ((lane >> 4) << 4);
            #pragma unroll
            for (int mt = 0; mt < 4; mt++) {
                const int row = warp_m + mt * 16 + (lane & 15);
                LDSM_X4(a[mt], aBase + SWZ128((uint32_t)(row * 128 + kbyte)));
            }
            #pragma unroll
            for (int nt2 = 0; nt2 < 2; nt2++) {
                const int row = warp_n + nt2 * 16 + (lane & 15);
                LDSM_X4(b[nt2], bBase + SWZ128((uint32_t)(row * 128 + kbyte)));
            }
            #pragma unroll
            for (int mt = 0; mt < 4; mt++)
                #pragma unroll
                for (int nt = 0; nt < 4; nt++) {
                    const uint32_t b0 = b[nt >> 1][(nt & 1) ? 1 : 0];
                    const uint32_t b1 = b[nt >> 1][(nt & 1) ? 3 : 2];
                    MMA16816(d[mt][nt], a[mt], b0, b1);
                }
        }
    }

    #pragma unroll
    for (int mt = 0; mt < 4; mt++) {
        const int row = m0 + warp_m + mt * 16 + (lane >> 2);
        #pragma unroll
        for (int nt = 0; nt < 4; nt++) {
            const int col = n0 + warp_n + nt * 8 + (lane & 3) * 2;
            float bx = 0.0f, by = 0.0f;
            if (bias) { bx = bias[col]; by = bias[col + 1]; }
            float v00 = d[mt][nt][0] + bx, v01 = d[mt][nt][1] + by;
            float v10 = d[mt][nt][2] + bx, v11 = d[mt][nt][3] + by;
            if constexpr (sizeof(OT) == 2) {
                *(__half2*)((__half*)C + (size_t)row * N + col) =
                    __floats2half2_rn(v00, v01);
                *(__half2*)((__half*)C + (size_t)(row + 8) * N + col) =
                    __floats2half2_rn(v10, v11);
            } else {
                float2 a0 = { v00, v01 }, a1 = { v10, v11 };
                *(float2*)((float*)C + (size_t)row * N + col)       = a0;
                *(float2*)((float*)C + (size_t)(row + 8) * N + col) = a1;
            }
        }
    }
}

// ============================================================
// fp16 HMMA flash attention (causal), 3-stage KV pipeline,
// 2 CTAs/SM, pre-scaled Q fragments, ex2.approx softmax.
// HEAVY-FIRST: q0 = (gridDim.x-1-blockIdx.x)*128 so the largest
// causal workloads start in the first wave (tail holds light tiles).
// ============================================================
#define FL_Q_OFF  0                    // 16 KB
#define FL_KV_OFF 16384                // 3 stages x (K 8K + V 8K)
#define FL_STAGE  16384
#define FL_SMEM   (16384 + 3 * FL_STAGE)   // 64 KB

__global__ __launch_bounds__(256, 2)
void flash_hmma(const __half* __restrict__ QKV,
                __half* __restrict__ Ctx)
{
    extern __shared__ char sm[];
    const uint32_t smem_base = smem_u32(sm);
    const int tid  = threadIdx.x;
    const int lane = tid & 31;
    const int wid  = tid >> 5;
    const int warp_m = wid * 16;
    const int q0 = (gridDim.x - 1 - blockIdx.x) * 128;   // heavy-first
    const int h  = blockIdx.y;
    const int b  = blockIdx.z;

    const size_t rowBase = (size_t)b * SEQ * QKV_LD + (size_t)h * HDIM;
    const __half* Q = QKV + rowBase;
    const __half* K = QKV + rowBase + DMODEL;
    const __half* V = QKV + rowBase + 2 * DMODEL;

    const int ntiles = (q0 + 128) / 64;

    auto load_kv = [&](int jt, int stage) {
        const uint32_t kBase = smem_base + FL_KV_OFF + stage * FL_STAGE;
        const uint32_t vBase = kBase + 8192;
        const int k0 = jt * 64;
        #pragma unroll
        for (int t = 0; t < 2; t++) {
            int g   = tid + t * 256;
            int row = g >> 3;
            int seg = g & 7;
            uint32_t sw = SWZ128((uint32_t)(row * 128 + seg * 16));
            CP_ASYNC16(kBase + sw, (const char*)(K + (size_t)(k0 + row) * QKV_LD + seg * 8));
            CP_ASYNC16(vBase + sw, (const char*)(V + (size_t)(k0 + row) * QKV_LD + seg * 8));
        }
        CP_ASYNC_COMMIT();
    };

    {
        #pragma unroll
        for (int t = 0; t < 4; t++) {
            int g   = tid + t * 256;
            int row = g >> 3;
            int seg = g & 7;
            uint32_t sw = SWZ128((uint32_t)(row * 128 + seg * 16));
            CP_ASYNC16(smem_base + FL_Q_OFF + sw,
                       (const char*)(Q + (size_t)(q0 + row) * QKV_LD + seg * 8));
        }
        CP_ASYNC_COMMIT();
    }
    load_kv(0, 0);
    if (ntiles > 1) load_kv(1, 1);

    if (ntiles > 1) {
        asm volatile("cp.async.wait_group 1;" ::: "memory");
    } else {
        asm volatile("cp.async.wait_group 0;" ::: "memory");
    }
    __syncthreads();

    // Q fragments, pre-scaled by FL_SCALE in fp16 (16 HMUL2, once)
    uint32_t qa[4][4];
    {
        __half2 a2 = __float2half2_rn(FL_SCALE);
        const uint32_t au = *reinterpret_cast<uint32_t*>(&a2);
        #pragma unroll
        for (int ks = 0; ks < 4; ks++) {
            const int row   = warp_m + (lane & 15);
            const int kbyte = ks * 32 + ((lane >> 4) << 4);
            LDSM_X4(qa[ks], smem_base + FL_Q_OFF + SWZ128((uint32_t)(row * 128 + kbyte)));
            #pragma unroll
            for (int i = 0; i < 4; i++) qa[ks][i] = hmul2u(qa[ks][i], au);
        }
    }

    float m1 = -1e30f, m2 = -1e30f, l1 = 0.0f, l2 = 0.0f;
    float o[8][4];
    #pragma unroll
    for (int t = 0; t < 8; t++)
        #pragma unroll
        for (int r = 0; r < 4; r++) o[t][r] = 0.0f;

    const int g = lane >> 2;
    const int r1 = q0 + warp_m + g;
    const int r2 = r1 + 8;
    const int cbase = (lane & 3) * 2;

    for (int jt = 0; jt < ntiles; jt++) {
        if (jt > 0) {
            if (jt + 1 < ntiles) {
                asm volatile("cp.async.wait_group 1;" ::: "memory");
            } else {
                asm volatile("cp.async.wait_group 0;" ::: "memory");
            }
            __syncthreads();
        }
        if (jt + 2 < ntiles) load_kv(jt + 2, (jt + 2) % 3);

        const int k0 = jt * 64;
        const uint32_t kBase = smem_base + FL_KV_OFF + (jt % 3) * FL_STAGE;
        const uint32_t vBase = kBase + 8192;

        // ---- S = (alpha*Q) K^T  (log2 domain) ----
        float s[8][4];
        #pragma unroll
        for (int t = 0; t < 8; t++)
            #pragma unroll
            for (int r = 0; r < 4; r++) s[t][r] = 0.0f;

        #pragma unroll
        for (int ks = 0; ks < 4; ks++) {
            const int kbyte = ks * 32 + ((lane >> 4) << 4);
            #pragma unroll
            for (int nb = 0; nb < 4; nb++) {
                uint32_t kb[4];
                const int row = nb * 16 + (lane & 15);
                LDSM_X4(kb, kBase + SWZ128((uint32_t)(row * 128 + kbyte)));
                MMA16816(s[nb * 2],     qa[ks], kb[0], kb[2]);
                MMA16816(s[nb * 2 + 1], qa[ks], kb[1], kb[3]);
            }
        }

        // ---- causal mask ----
        if (k0 + 63 > q0 + warp_m) {
            #pragma unroll
            for (int t = 0; t < 8; t++) {
                const int c0 = k0 + t * 8 + cbase;
                if (c0 > r1)     s[t][0] = -1e30f;
                if (c0 + 1 > r1) s[t][1] = -1e30f;
                if (c0 > r2)     s[t][2] = -1e30f;
                if (c0 + 1 > r2) s[t][3] = -1e30f;
            }
        }

        // ---- online softmax (base-2, pre-scaled) ----
        float mx1 = -1e30f, mx2 = -1e30f;
        #pragma unroll
        for (int t = 0; t < 8; t++) {
            mx1 = fmaxf(mx1, fmaxf(s[t][0], s[t][1]));
            mx2 = fmaxf(mx2, fmaxf(s[t][2], s[t][3]));
        }
        mx1 = fmaxf(mx1, __shfl_xor_sync(0xffffffffu, mx1, 1));
        mx1 = fmaxf(mx1, __shfl_xor_sync(0xffffffffu, mx1, 2));
        mx2 = fmaxf(mx2, __shfl_xor_sync(0xffffffffu, mx2, 1));
        mx2 = fmaxf(mx2, __shfl_xor_sync(0xffffffffu, mx2, 2));

        const float mn1 = fmaxf(m1, mx1), mn2 = fmaxf(m2, mx2);
        const float sc1 = ex2(m1 - mn1);
        const float sc2 = ex2(m2 - mn2);
        float sum1 = 0.0f, sum2 = 0.0f;
        #pragma unroll
        for (int t = 0; t < 8; t++) {
            s[t][0] = ex2(s[t][0] - mn1); sum1 += s[t][0];
            s[t][1] = ex2(s[t][1] - mn1); sum1 += s[t][1];
            s[t][2] = ex2(s[t][2] - mn2); sum2 += s[t][2];
            s[t][3] = ex2(s[t][3] - mn2); sum2 += s[t][3];
        }
        sum1 += __shfl_xor_sync(0xffffffffu, sum1, 1);
        sum1 += __shfl_xor_sync(0xffffffffu, sum1, 2);
        sum2 += __shfl_xor_sync(0xffffffffu, sum2, 1);
        sum2 += __shfl_xor_sync(0xffffffffu, sum2, 2);

        l1 = l1 * sc1 + sum1;
        l2 = l2 * sc2 + sum2;
        m1 = mn1; m2 = mn2;

        #pragma unroll
        for (int t = 0; t < 8; t++) {
            o[t][0] *= sc1; o[t][1] *= sc1;
            o[t][2] *= sc2; o[t][3] *= sc2;
        }

        // ---- P fragments ----
        uint32_t pa[4][4];
        #pragma unroll
        for (int ks = 0; ks < 4; ks++) {
            pa[ks][0] = packh2(s[2 * ks][0],     s[2 * ks][1]);
            pa[ks][1] = packh2(s[2 * ks][2],     s[2 * ks][3]);
            pa[ks][2] = packh2(s[2 * ks + 1][0], s[2 * ks + 1][1]);
            pa[ks][3] = packh2(s[2 * ks + 1][2], s[2 * ks + 1][3]);
        }

        // ---- O += P V ----
        #pragma unroll
        for (int ks = 0; ks < 4; ks++) {
            const int crow = ks * 16 + (lane & 15);
            #pragma unroll
            for (int db = 0; db < 4; db++) {
                uint32_t vb[4];
                const int dbyte = db * 32 + ((lane >> 4) << 4);
                LDSM_X4_T(vb, vBase + SWZ128((uint32_t)(crow * 128 + dbyte)));
                MMA16816(o[db * 2],     pa[ks], vb[0], vb[1]);
                MMA16816(o[db * 2 + 1], pa[ks], vb[2], vb[3]);
            }
        }
    }

    // ---- normalize + write ctx ----
    const size_t ctxBase = (size_t)b * SEQ * DMODEL + (size_t)h * HDIM;
    const float inv1 = 1.0f / l1, inv2 = 1.0f / l2;
    #pragma unroll
    for (int t = 0; t < 8; t++) {
        const int col = t * 8 + cbase;
        *(__half2*)(Ctx + ctxBase + (size_t)r1 * DMODEL + col) =
            __floats2half2_rn(o[t][0] * inv1, o[t][1] * inv1);
        *(__half2*)(Ctx + ctxBase + (size_t)r2 * DMODEL + col) =
            __floats2half2_rn(o[t][2] * inv2, o[t][3] * inv2);
    }
}

// ============================================================
extern "C" void kernel_launch(void* const* d_in, const int* in_sizes, int n_in,
                              void* d_out, int out_size)
{
    const float* x  = (const float*)d_in[0];
    const float* Wq = (const float*)d_in[1];
    const float* Wk = (const float*)d_in[2];
    const float* Wv = (const float*)d_in[3];
    const float* Wo = (const float*)d_in[4];
    const float* bo = (const float*)d_in[5];
    float* out = (float*)d_out;

    __half *QKVh, *Ch, *Xh, *Wcat, *Woh;
    cudaGetSymbolAddress((void**)&QKVh, g_QKV);
    cudaGetSymbolAddress((void**)&Ch,   g_Ctxh);
    cudaGetSymbolAddress((void**)&Xh,   g_Xh);
    cudaGetSymbolAddress((void**)&Wcat, g_Wcat);
    cudaGetSymbolAddress((void**)&Woh,  g_Woh);

    cudaFuncSetAttribute(hgemm_nt<__half>,
                         cudaFuncAttributeMaxDynamicSharedMemorySize, HG_SMEM);
    cudaFuncSetAttribute(hgemm_nt<float>,
                         cudaFuncAttributeMaxDynamicSharedMemorySize, HG_SMEM);
    cudaFuncSetAttribute(flash_hmma,
                         cudaFuncAttributeMaxDynamicSharedMemorySize, FL_SMEM);

    const int nX = MTOT * DMODEL, nW = DMODEL * DMODEL;
    f2h_kernel <<<nX / 4 / 256, 256>>>(x, Xh, nX);
    f2h3_kernel<<<3 * nW / 4 / 256, 256>>>(Wq, Wk, Wv, Wcat, nW);
    f2h_kernel <<<nW / 4 / 256, 256>>>(Wo, Woh, nW);

    // fused QKV projection: [4096 x 3072]
    dim3 gQKV(QKV_LD / 128, MTOT / 128);    // (24, 32)
    hgemm_nt<__half><<<gQKV, 256, HG_SMEM>>>(Xh, Wcat, nullptr, QKVh,
                                             MTOT, QKV_LD, DMODEL);

    dim3 gFa(SEQ / 128, NHEADS, BATCH);     // (16, 16, 2)
    flash_hmma<<<gFa, 256, FL_SMEM>>>(QKVh, Ch);

    dim3 gO(DMODEL / 128, MTOT / 128);      // (8, 32)
    hgemm_nt<float><<<gO, 256, HG_SMEM>>>(Ch, Woh, bo, out, MTOT, DMODEL, DMODEL);
}

// round 17
// speedup vs baseline: 1.0633x; 1.0263x over previous
#include <cuda_runtime.h>
#include <cuda_fp16.h>
#include <math.h>
#include <stdint.h>

// Problem constants
#define BATCH 2
#define SEQ   2048
#define DMODEL 1024
#define NHEADS 16
#define HDIM  64
#define MTOT  (BATCH * SEQ)            // 4096
#define QKV_LD (3 * DMODEL)            // 3072
#define FL_SCALE 0.1803368801111244f   // 0.125 * log2(e)

// -------- scratch (no allocations allowed -> __device__ globals) --------
__device__ __half g_QKV [(size_t)MTOT * QKV_LD];          // fused QKV output
__device__ __half g_Ctxh[(size_t)MTOT * DMODEL];
__device__ __half g_Xh  [(size_t)MTOT * DMODEL];
__device__ __half g_Wcat[(size_t)QKV_LD * DMODEL];        // [Wq;Wk;Wv]
__device__ __half g_Woh [(size_t)DMODEL * DMODEL];

// ================= helpers =================
__device__ __forceinline__ uint32_t smem_u32(const void* p) {
    uint32_t a;
    asm("{ .reg .u64 t; cvta.to.shared.u64 t, %1; cvt.u32.u64 %0, t; }"
        : "=r"(a) : "l"(p));
    return a;
}

#define SWZ128(x) ((x) ^ (((x) >> 3) & 0x70))

#define CP_ASYNC16(dst, src) \
    asm volatile("cp.async.cg.shared.global [%0], [%1], 16;" \
                 :: "r"(dst), "l"(src) : "memory")
#define CP_ASYNC_COMMIT() asm volatile("cp.async.commit_group;" ::: "memory")

#define LDSM_X4(r, addr) \
    asm volatile("ldmatrix.sync.aligned.m8n8.x4.shared.b16 {%0,%1,%2,%3}, [%4];" \
        : "=r"((r)[0]), "=r"((r)[1]), "=r"((r)[2]), "=r"((r)[3]) : "r"(addr))

#define LDSM_X4_T(r, addr) \
    asm volatile("ldmatrix.sync.aligned.m8n8.x4.trans.shared.b16 {%0,%1,%2,%3}, [%4];" \
        : "=r"((r)[0]), "=r"((r)[1]), "=r"((r)[2]), "=r"((r)[3]) : "r"(addr))

#define MMA16816(d, a, b0, b1) \
    asm volatile("mma.sync.aligned.m16n8k16.row.col.f32.f16.f16.f32 " \
        "{%0,%1,%2,%3}, {%4,%5,%6,%7}, {%8,%9}, {%0,%1,%2,%3};" \
        : "+f"((d)[0]), "+f"((d)[1]), "+f"((d)[2]), "+f"((d)[3]) \
        : "r"((a)[0]), "r"((a)[1]), "r"((a)[2]), "r"((a)[3]), "r"(b0), "r"(b1))

__device__ __forceinline__ uint32_t packh2(float a, float b) {
    __half2 h = __floats2half2_rn(a, b);
    return *reinterpret_cast<uint32_t*>(&h);
}

__device__ __forceinline__ uint32_t hmul2u(uint32_t a, uint32_t b) {
    __half2 r = __hmul2(*reinterpret_cast<__half2*>(&a),
                        *reinterpret_cast<__half2*>(&b));
    return *reinterpret_cast<uint32_t*>(&r);
}

// single-instruction exponential (base 2); flushes large-negative to +0
__device__ __forceinline__ float ex2(float x) {
    float y;
    asm("ex2.approx.f32 %0, %1;" : "=f"(y) : "f"(x));
    return y;
}

// ============================================================
// conversions
// ============================================================
__global__ void f2h_kernel(const float* __restrict__ src,
                           __half* __restrict__ dst, int n)
{
    int i = (blockIdx.x * blockDim.x + threadIdx.x) * 4;
    if (i >= n) return;
    float4 v = *(const float4*)(src + i);
    *(__half2*)(dst + i)     = __floats2half2_rn(v.x, v.y);
    *(__half2*)(dst + i + 2) = __floats2half2_rn(v.z, v.w);
}

__global__ void f2h3_kernel(const float* __restrict__ s0,
                            const float* __restrict__ s1,
                            const float* __restrict__ s2,
                            __half* __restrict__ dst, int nPer)
{
    int i = (blockIdx.x * blockDim.x + threadIdx.x) * 4;
    if (i >= 3 * nPer) return;
    const float* src = (i < nPer) ? s0 : (i < 2 * nPer) ? s1 : s2;
    int j = i - ((i < nPer) ? 0 : (i < 2 * nPer) ? nPer : 2 * nPer);
    float4 v = *(const float4*)(src + j);
    *(__half2*)(dst + i)     = __floats2half2_rn(v.x, v.y);
    *(__half2*)(dst + i + 2) = __floats2half2_rn(v.z, v.w);
}

// ============================================================
// fp16 HMMA GEMM (NT): C[M,N] = A[M,K] * B[N,K]^T (+bias)
// 128x128 CTA tile, BK=64, 8 warps, 3-stage cp.async pipeline
// with ONE __syncthreads per chunk, 2 CTAs/SM.  (round-10 version)
// ============================================================
#define HG_STAGE 32768                 // A 16K + B 16K per stage
#define HG_SMEM  (3 * HG_STAGE)        // 96 KB

template <typename OT>
__global__ __launch_bounds__(256, 2)
void hgemm_nt(const __half* __restrict__ A,
              const __half* __restrict__ B,
              const float* __restrict__ bias,
              OT* __restrict__ C,
              int M, int N, int K)
{
    extern __shared__ char sm[];
    const uint32_t smem_base = smem_u32(sm);
    const int tid  = threadIdx.x;
    const int lane = tid & 31;
    const int wid  = tid >> 5;
    const int m0 = blockIdx.y * 128;
    const int n0 = blockIdx.x * 128;
    const int warp_m = (wid >> 2) * 64;
    const int warp_n = (wid & 3) * 32;

    float d[4][4][4];
    #pragma unroll
    for (int mt = 0; mt < 4; mt++)
        #pragma unroll
        for (int nt = 0; nt < 4; nt++)
            #pragma unroll
            for (int r = 0; r < 4; r++) d[mt][nt][r] = 0.0f;

    const int nchunks = K / 64;

    auto load_chunk = [&](int c, int stage) {
        const uint32_t aBase = smem_base + stage * HG_STAGE;
        const uint32_t bBase = aBase + 16384;
        const char* Ag = (const char*)(A + (size_t)m0 * K + c * 64);
        const char* Bg = (const char*)(B + (size_t)n0 * K + c * 64);
        #pragma unroll
        for (int t = 0; t < 4; t++) {
            int g   = tid + t * 256;
            int row = g >> 3;
            int seg = g & 7;
            uint32_t sw = SWZ128((uint32_t)(row * 128 + seg * 16));
            CP_ASYNC16(aBase + sw, Ag + (size_t)row * K * 2 + seg * 16);
            CP_ASYNC16(bBase + sw, Bg + (size_t)row * K * 2 + seg * 16);
        }
        CP_ASYNC_COMMIT();
    };

    load_chunk(0, 0);
    if (nchunks > 1) load_chunk(1, 1);

    for (int c = 0; c < nchunks; c++) {
        if (c + 1 < nchunks) {
            asm volatile("cp.async.wait_group 1;" ::: "memory");
        } else {
            asm volatile("cp.async.wait_group 0;" ::: "memory");
        }
        __syncthreads();
        if (c + 2 < nchunks) load_chunk(c + 2, (c + 2) % 3);

        const uint32_t aBase = smem_base + (c % 3) * HG_STAGE;
        const uint32_t bBase = aBase + 16384;

        #pragma unroll
        for (int ks = 0; ks < 4; ks++) {
            uint32_t a[4][4], b[2][4];
            const int kbyte = ks * 32 + ((lane >> 4) << 4);
            #pragma unroll
            for (int mt = 0; mt < 4; mt++) {
                const int row = warp_m + mt * 16 + (lane & 15);
                LDSM_X4(a[mt], aBase + SWZ128((uint32_t)(row * 128 + kbyte)));
            }
            #pragma unroll
            for (int nt2 = 0; nt2 < 2; nt2++) {
                const int row = warp_n + nt2 * 16 + (lane & 15);
                LDSM_X4(b[nt2], bBase + SWZ128((uint32_t)(row * 128 + kbyte)));
            }
            #pragma unroll
            for (int mt = 0; mt < 4; mt++)
                #pragma unroll
                for (int nt = 0; nt < 4; nt++) {
                    const uint32_t b0 = b[nt >> 1][(nt & 1) ? 1 : 0];
                    const uint32_t b1 = b[nt >> 1][(nt & 1) ? 3 : 2];
                    MMA16816(d[mt][nt], a[mt], b0, b1);
                }
        }
    }

    #pragma unroll
    for (int mt = 0; mt < 4; mt++) {
        const int row = m0 + warp_m + mt * 16 + (lane >> 2);
        #pragma unroll
        for (int nt = 0; nt < 4; nt++) {
            const int col = n0 + warp_n + nt * 8 + (lane & 3) * 2;
            float bx = 0.0f, by = 0.0f;
            if (bias) { bx = bias[col]; by = bias[col + 1]; }
            float v00 = d[mt][nt][0] + bx, v01 = d[mt][nt][1] + by;
            float v10 = d[mt][nt][2] + bx, v11 = d[mt][nt][3] + by;
            if constexpr (sizeof(OT) == 2) {
                *(__half2*)((__half*)C + (size_t)row * N + col) =
                    __floats2half2_rn(v00, v01);
                *(__half2*)((__half*)C + (size_t)(row + 8) * N + col) =
                    __floats2half2_rn(v10, v11);
            } else {
                float2 a0 = { v00, v01 }, a1 = { v10, v11 };
                *(float2*)((float*)C + (size_t)row * N + col)       = a0;
                *(float2*)((float*)C + (size_t)(row + 8) * N + col) = a1;
            }
        }
    }
}

// ============================================================
// fp16 HMMA flash attention (causal), 3-stage KV pipeline.
// NEW: 4 warps / 128 threads / 64 q-rows per CTA, 4 CTAs/SM.
// Four independent barrier/pipeline domains per SM hide each
// other's tile-boundary bubbles; LDSM duplication halves.
// ============================================================
#define FL_Q_OFF  0                    // 8 KB (64 rows x 128B)
#define FL_KV_OFF 8192                 // 3 stages x (K 8K + V 8K)
#define FL_STAGE  16384
#define FL_SMEM   (8192 + 3 * FL_STAGE)    // 56 KB
#define FL_THREADS 128

__global__ __launch_bounds__(FL_THREADS, 4)
void flash_hmma(const __half* __restrict__ QKV,
                __half* __restrict__ Ctx)
{
    extern __shared__ char sm[];
    const uint32_t smem_base = smem_u32(sm);
    const int tid  = threadIdx.x;
    const int lane = tid & 31;
    const int wid  = tid >> 5;          // 0..3
    const int warp_m = wid * 16;
    const int q0 = (gridDim.x - 1 - blockIdx.x) * 64;   // heavy-first
    const int h  = blockIdx.y;
    const int b  = blockIdx.z;

    const size_t rowBase = (size_t)b * SEQ * QKV_LD + (size_t)h * HDIM;
    const __half* Q = QKV + rowBase;
    const __half* K = QKV + rowBase + DMODEL;
    const __half* V = QKV + rowBase + 2 * DMODEL;

    const int ntiles = (q0 + 64) / 64;

    auto load_kv = [&](int jt, int stage) {
        const uint32_t kBase = smem_base + FL_KV_OFF + stage * FL_STAGE;
        const uint32_t vBase = kBase + 8192;
        const int k0 = jt * 64;
        #pragma unroll
        for (int t = 0; t < 4; t++) {
            int g   = tid + t * FL_THREADS;   // 0..511
            int row = g >> 3;
            int seg = g & 7;
            uint32_t sw = SWZ128((uint32_t)(row * 128 + seg * 16));
            CP_ASYNC16(kBase + sw, (const char*)(K + (size_t)(k0 + row) * QKV_LD + seg * 8));
            CP_ASYNC16(vBase + sw, (const char*)(V + (size_t)(k0 + row) * QKV_LD + seg * 8));
        }
        CP_ASYNC_COMMIT();
    };

    {   // Q tile: 64 rows x 128B
        #pragma unroll
        for (int t = 0; t < 4; t++) {
            int g   = tid + t * FL_THREADS;   // 0..511
            int row = g >> 3;
            int seg = g & 7;
            uint32_t sw = SWZ128((uint32_t)(row * 128 + seg * 16));
            CP_ASYNC16(smem_base + FL_Q_OFF + sw,
                       (const char*)(Q + (size_t)(q0 + row) * QKV_LD + seg * 8));
        }
        CP_ASYNC_COMMIT();
    }
    load_kv(0, 0);
    if (ntiles > 1) load_kv(1, 1);

    if (ntiles > 1) {
        asm volatile("cp.async.wait_group 1;" ::: "memory");
    } else {
        asm volatile("cp.async.wait_group 0;" ::: "memory");
    }
    __syncthreads();

    // Q fragments, pre-scaled by FL_SCALE in fp16 (16 HMUL2, once)
    uint32_t qa[4][4];
    {
        __half2 a2 = __float2half2_rn(FL_SCALE);
        const uint32_t au = *reinterpret_cast<uint32_t*>(&a2);
        #pragma unroll
        for (int ks = 0; ks < 4; ks++) {
            const int row   = warp_m + (lane & 15);
            const int kbyte = ks * 32 + ((lane >> 4) << 4);
            LDSM_X4(qa[ks], smem_base + FL_Q_OFF + SWZ128((uint32_t)(row * 128 + kbyte)));
            #pragma unroll
            for (int i = 0; i < 4; i++) qa[ks][i] = hmul2u(qa[ks][i], au);
        }
    }

    float m1 = -1e30f, m2 = -1e30f, l1 = 0.0f, l2 = 0.0f;
    float o[8][4];
    #pragma unroll
    for (int t = 0; t < 8; t++)
        #pragma unroll
        for (int r = 0; r < 4; r++) o[t][r] = 0.0f;

    const int g = lane >> 2;
    const int r1 = q0 + warp_m + g;
    const int r2 = r1 + 8;
    const int cbase = (lane & 3) * 2;

    for (int jt = 0; jt < ntiles; jt++) {
        if (jt > 0) {
            if (jt + 1 < ntiles) {
                asm volatile("cp.async.wait_group 1;" ::: "memory");
            } else {
                asm volatile("cp.async.wait_group 0;" ::: "memory");
            }
            __syncthreads();
        }
        if (jt + 2 < ntiles) load_kv(jt + 2, (jt + 2) % 3);

        const int k0 = jt * 64;
        const uint32_t kBase = smem_base + FL_KV_OFF + (jt % 3) * FL_STAGE;
        const uint32_t vBase = kBase + 8192;

        // ---- S = (alpha*Q) K^T  (log2 domain) ----
        float s[8][4];
        #pragma unroll
        for (int t = 0; t < 8; t++)
            #pragma unroll
            for (int r = 0; r < 4; r++) s[t][r] = 0.0f;

        #pragma unroll
        for (int ks = 0; ks < 4; ks++) {
            const int kbyte = ks * 32 + ((lane >> 4) << 4);
            #pragma unroll
            for (int nb = 0; nb < 4; nb++) {
                uint32_t kb[4];
                const int row = nb * 16 + (lane & 15);
                LDSM_X4(kb, kBase + SWZ128((uint32_t)(row * 128 + kbyte)));
                MMA16816(s[nb * 2],     qa[ks], kb[0], kb[2]);
                MMA16816(s[nb * 2 + 1], qa[ks], kb[1], kb[3]);
            }
        }

        // ---- causal mask ----
        if (k0 + 63 > q0 + warp_m) {
            #pragma unroll
            for (int t = 0; t < 8; t++) {
                const int c0 = k0 + t * 8 + cbase;
                if (c0 > r1)     s[t][0] = -1e30f;
                if (c0 + 1 > r1) s[t][1] = -1e30f;
                if (c0 > r2)     s[t][2] = -1e30f;
                if (c0 + 1 > r2) s[t][3] = -1e30f;
            }
        }

        // ---- online softmax (base-2, pre-scaled) ----
        float mx1 = -1e30f, mx2 = -1e30f;
        #pragma unroll
        for (int t = 0; t < 8; t++) {
            mx1 = fmaxf(mx1, fmaxf(s[t][0], s[t][1]));
            mx2 = fmaxf(mx2, fmaxf(s[t][2], s[t][3]));
        }
        mx1 = fmaxf(mx1, __shfl_xor_sync(0xffffffffu, mx1, 1));
        mx1 = fmaxf(mx1, __shfl_xor_sync(0xffffffffu, mx1, 2));
        mx2 = fmaxf(mx2, __shfl_xor_sync(0xffffffffu, mx2, 1));
        mx2 = fmaxf(mx2, __shfl_xor_sync(0xffffffffu, mx2, 2));

        const float mn1 = fmaxf(m1, mx1), mn2 = fmaxf(m2, mx2);
        const float sc1 = ex2(m1 - mn1);
        const float sc2 = ex2(m2 - mn2);
        float sum1 = 0.0f, sum2 = 0.0f;
        #pragma unroll
        for (int t = 0; t < 8; t++) {
            s[t][0] = ex2(s[t][0] - mn1); sum1 += s[t][0];
            s[t][1] = ex2(s[t][1] - mn1); sum1 += s[t][1];
            s[t][2] = ex2(s[t][2] - mn2); sum2 += s[t][2];
            s[t][3] = ex2(s[t][3] - mn2); sum2 += s[t][3];
        }
        sum1 += __shfl_xor_sync(0xffffffffu, sum1, 1);
        sum1 += __shfl_xor_sync(0xffffffffu, sum1, 2);
        sum2 += __shfl_xor_sync(0xffffffffu, sum2, 1);
        sum2 += __shfl_xor_sync(0xffffffffu, sum2, 2);

        l1 = l1 * sc1 + sum1;
        l2 = l2 * sc2 + sum2;
        m1 = mn1; m2 = mn2;

        #pragma unroll
        for (int t = 0; t < 8; t++) {
            o[t][0] *= sc1; o[t][1] *= sc1;
            o[t][2] *= sc2; o[t][3] *= sc2;
        }

        // ---- P fragments ----
        uint32_t pa[4][4];
        #pragma unroll
        for (int ks = 0; ks < 4; ks++) {
            pa[ks][0] = packh2(s[2 * ks][0],     s[2 * ks][1]);
            pa[ks][1] = packh2(s[2 * ks][2],     s[2 * ks][3]);
            pa[ks][2] = packh2(s[2 * ks + 1][0], s[2 * ks + 1][1]);
            pa[ks][3] = packh2(s[2 * ks + 1][2], s[2 * ks + 1][3]);
        }

        // ---- O += P V ----
        #pragma unroll
        for (int ks = 0; ks < 4; ks++) {
            const int crow = ks * 16 + (lane & 15);
            #pragma unroll
            for (int db = 0; db < 4; db++) {
                uint32_t vb[4];
                const int dbyte = db * 32 + ((lane >> 4) << 4);
                LDSM_X4_T(vb, vBase + SWZ128((uint32_t)(crow * 128 + dbyte)));
                MMA16816(o[db * 2],     pa[ks], vb[0], vb[1]);
                MMA16816(o[db * 2 + 1], pa[ks], vb[2], vb[3]);
            }
        }
    }

    // ---- normalize + write ctx ----
    const size_t ctxBase = (size_t)b * SEQ * DMODEL + (size_t)h * HDIM;
    const float inv1 = 1.0f / l1, inv2 = 1.0f / l2;
    #pragma unroll
    for (int t = 0; t < 8; t++) {
        const int col = t * 8 + cbase;
        *(__half2*)(Ctx + ctxBase + (size_t)r1 * DMODEL + col) =
            __floats2half2_rn(o[t][0] * inv1, o[t][1] * inv1);
        *(__half2*)(Ctx + ctxBase + (size_t)r2 * DMODEL + col) =
            __floats2half2_rn(o[t][2] * inv2, o[t][3] * inv2);
    }
}

// ============================================================
extern "C" void kernel_launch(void* const* d_in, const int* in_sizes, int n_in,
                              void* d_out, int out_size)
{
    const float* x  = (const float*)d_in[0];
    const float* Wq = (const float*)d_in[1];
    const float* Wk = (const float*)d_in[2];
    const float* Wv = (const float*)d_in[3];
    const float* Wo = (const float*)d_in[4];
    const float* bo = (const float*)d_in[5];
    float* out = (float*)d_out;

    __half *QKVh, *Ch, *Xh, *Wcat, *Woh;
    cudaGetSymbolAddress((void**)&QKVh, g_QKV);
    cudaGetSymbolAddress((void**)&Ch,   g_Ctxh);
    cudaGetSymbolAddress((void**)&Xh,   g_Xh);
    cudaGetSymbolAddress((void**)&Wcat, g_Wcat);
    cudaGetSymbolAddress((void**)&Woh,  g_Woh);

    cudaFuncSetAttribute(hgemm_nt<__half>,
                         cudaFuncAttributeMaxDynamicSharedMemorySize, HG_SMEM);
    cudaFuncSetAttribute(hgemm_nt<float>,
                         cudaFuncAttributeMaxDynamicSharedMemorySize, HG_SMEM);
    cudaFuncSetAttribute(flash_hmma,
                         cudaFuncAttributeMaxDynamicSharedMemorySize, FL_SMEM);

    const int nX = MTOT * DMODEL, nW = DMODEL * DMODEL;
    f2h_kernel <<<nX / 4 / 256, 256>>>(x, Xh, nX);
    f2h3_kernel<<<3 * nW / 4 / 256, 256>>>(Wq, Wk, Wv, Wcat, nW);
    f2h_kernel <<<nW / 4 / 256, 256>>>(Wo, Woh, nW);

    // fused QKV projection: [4096 x 3072]
    dim3 gQKV(QKV_LD / 128, MTOT / 128);    // (24, 32)
    hgemm_nt<__half><<<gQKV, 256, HG_SMEM>>>(Xh, Wcat, nullptr, QKVh,
                                             MTOT, QKV_LD, DMODEL);

    dim3 gFa(SEQ / 64, NHEADS, BATCH);      // (32, 16, 2) = 1024 CTAs
    flash_hmma<<<gFa, FL_THREADS, FL_SMEM>>>(QKVh, Ch);

    dim3 gO(DMODEL / 128, MTOT / 128);      // (8, 32)
    hgemm_nt<float><<<gO, 256, HG_SMEM>>>(Ch, Woh, bo, out, MTOT, DMODEL, DMODEL);
}